// round 4
// baseline (speedup 1.0000x reference)
#include <cuda_runtime.h>
#include <cstdint>

// Embedding gather via bulk-async (TMA) copies.
// input: [32768] int32, weight: [50257, 512] f32 (2048B rows), out: [32768, 512] f32
//
// Rationale: LDG-based gather is capped by the per-SM outstanding-miss
// tracker (~55 lines in flight -> ~3.2TB/s). cp.async.bulk moves 2KB per
// request through the TMA/LTS path (bypasses L1, per-transaction tracking),
// so bytes-in-flight is bounded only by smem staging, not the miss queue.
//
// Each CTA: 16 tokens. One thread issues 16x 2KB bulk loads (gmem->smem)
// under a single mbarrier (expect_tx = 32KB), waits, then issues 16x 2KB
// bulk stores (smem->gmem) and drains the bulk group. ~6 CTAs/SM resident
// (32KB smem each) gives ~200KB/SM in flight — far above the Little's-law
// requirement for 8TB/s.

#define TOK_PER_CTA 16
#define ROW_BYTES   2048

__global__ __launch_bounds__(32) void embed_bulk_gather(
    const int* __restrict__ idx,
    const char* __restrict__ weight,
    char* __restrict__ out,
    int n_tokens)
{
    __shared__ alignas(1024) char buf[TOK_PER_CTA * ROW_BYTES];
    __shared__ alignas(8) unsigned long long mbar;
    __shared__ int rows[TOK_PER_CTA];

    const int tid  = threadIdx.x;
    const int base = blockIdx.x * TOK_PER_CTA;
    if (base >= n_tokens) return;

    if (tid < TOK_PER_CTA) rows[tid] = idx[base + tid];

    const uint32_t mbar_a = (uint32_t)__cvta_generic_to_shared(&mbar);
    const uint32_t buf_a  = (uint32_t)__cvta_generic_to_shared(buf);

    if (tid == 0) {
        asm volatile("mbarrier.init.shared.b64 [%0], 1;" :: "r"(mbar_a) : "memory");
    }
    __syncthreads();   // rows[] visible + mbar initialized

    if (tid == 0) {
        // Expect all 16 rows' bytes on one barrier.
        asm volatile("mbarrier.arrive.expect_tx.shared.b64 _, [%0], %1;"
                     :: "r"(mbar_a), "r"(TOK_PER_CTA * ROW_BYTES) : "memory");

        #pragma unroll
        for (int i = 0; i < TOK_PER_CTA; i++) {
            const char* src = weight + (long long)rows[i] * ROW_BYTES;
            asm volatile(
                "cp.async.bulk.shared::cta.global.mbarrier::complete_tx::bytes "
                "[%0], [%1], %2, [%3];"
                :: "r"(buf_a + i * ROW_BYTES), "l"(src), "r"(ROW_BYTES), "r"(mbar_a)
                : "memory");
        }

        // Wait for all loads (phase 0), HW-sleep try_wait loop.
        {
            uint32_t done;
            asm volatile(
                "{\n\t"
                ".reg .pred p;\n\t"
                "WAIT_LOOP_%=:\n\t"
                "mbarrier.try_wait.parity.shared.b64 p, [%1], %2, 0x989680;\n\t"
                "selp.b32 %0, 1, 0, p;\n\t"
                "@!p bra.uni WAIT_LOOP_%=;\n\t"
                "}"
                : "=r"(done) : "r"(mbar_a), "r"(0) : "memory");
            (void)done;
        }

        // Bulk stores smem -> gmem.
        #pragma unroll
        for (int i = 0; i < TOK_PER_CTA; i++) {
            char* dst = out + (long long)(base + i) * ROW_BYTES;
            asm volatile(
                "cp.async.bulk.global.shared::cta.bulk_group [%0], [%1], %2;"
                :: "l"(dst), "r"(buf_a + i * ROW_BYTES), "r"(ROW_BYTES)
                : "memory");
        }
        asm volatile("cp.async.bulk.commit_group;" ::: "memory");
        // Must drain before CTA exit (smem slot gets reused by next CTA).
        asm volatile("cp.async.bulk.wait_group 0;" ::: "memory");
    }
}

extern "C" void kernel_launch(void* const* d_in, const int* in_sizes, int n_in,
                              void* d_out, int out_size) {
    const int*  idx    = (const int*)d_in[0];     // [8*4096] int32
    const char* weight = (const char*)d_in[1];    // [50257*512] f32 rows (2048B)
    char*       out    = (char*)d_out;

    int n_tokens = in_sizes[0];                   // 32768
    int blocks   = (n_tokens + TOK_PER_CTA - 1) / TOK_PER_CTA;  // 2048
    embed_bulk_gather<<<blocks, 32>>>(idx, weight, out, n_tokens);
}

// round 5
// speedup vs baseline: 1.2624x; 1.2624x over previous
#include <cuda_runtime.h>
#include <cstdint>

// Embedding gather: out[token, :] = weight[input[token], :]
// input: [32768] int32, weight: [50257, 512] f32, out: [32768, 512] f32
//
// Steady-state analysis: per replay the DRAM must move ~48MB unique weight
// rows + 67MB output writeback ~= 115MB; at 16.9us that's ~6.8TB/s, i.e.
// already ~85% of HBM spec. Remaining lever: shorten the per-warp dependent
// chain. Previously each warp did idx-LDG (~600cyc) -> weight-LDG (~600cyc)
// serially. Here a block stages its 8 indices with ONE coalesced load into
// smem; warps read their row id via LDS (29cyc), halving exposed latency.
//
// One warp per token row, 4 independent float4 loads per thread (MLP=4,
// the best-measured configuration), streaming stores keep output evict-first
// in L2 so weight rows stay resident for repeat hits.

#define WARPS_PER_CTA 8

__global__ __launch_bounds__(WARPS_PER_CTA * 32) void embed_gather_smem_idx(
    const int* __restrict__ idx,
    const float4* __restrict__ weight4,
    float4* __restrict__ out4,
    int n_tokens)
{
    __shared__ int s_rows[WARPS_PER_CTA];

    const int tid  = threadIdx.x;
    const int warp = tid >> 5;
    const int lane = tid & 31;
    const int base = blockIdx.x * WARPS_PER_CTA;

    // One coalesced load fetches all indices for this block.
    if (tid < WARPS_PER_CTA) {
        int t = base + tid;
        s_rows[tid] = (t < n_tokens) ? __ldg(idx + t) : 0;
    }
    __syncthreads();

    const int token = base + warp;
    if (token >= n_tokens) return;
    const int row = s_rows[warp];

    const float4* __restrict__ src = weight4 + (long long)row * 128 + lane;
    float4* __restrict__ dst       = out4    + (long long)token * 128 + lane;

    // 4 independent loads front-batched (MLP=4)
    float4 v0 = __ldg(src);
    float4 v1 = __ldg(src + 32);
    float4 v2 = __ldg(src + 64);
    float4 v3 = __ldg(src + 96);

    __stcs(dst,      v0);
    __stcs(dst + 32, v1);
    __stcs(dst + 64, v2);
    __stcs(dst + 96, v3);
}

extern "C" void kernel_launch(void* const* d_in, const int* in_sizes, int n_in,
                              void* d_out, int out_size) {
    const int*   idx    = (const int*)d_in[0];     // [8*4096] int32
    const float* weight = (const float*)d_in[1];   // [50257*512] f32
    float*       out    = (float*)d_out;

    int n_tokens = in_sizes[0];                    // 32768
    int blocks   = (n_tokens + WARPS_PER_CTA - 1) / WARPS_PER_CTA;  // 4096
    embed_gather_smem_idx<<<blocks, WARPS_PER_CTA * 32>>>(
        idx, (const float4*)weight, (float4*)out, n_tokens);
}